// round 9
// baseline (speedup 1.0000x reference)
#include <cuda_runtime.h>
#include <cuda_bf16.h>
#include <math.h>
#include <stdint.h>

#define BB 128
#define LL 64
#define HH 512
#define VOCAB 32000
#define TT 32
#define NSTEP 31
#define BL (BB*LL)       // 8192
#define NVB (VOCAB/128)  // 250

// ---------------- scratch (device globals; no allocation) ----------------
__device__ float g_encpart[BL*HH];
__device__ __nv_bfloat16 g_encpb[BL*HH];
__device__ __nv_bfloat16 g_encb[BL*HH];
__device__ __nv_bfloat16 g_a2b[BL*HH];
__device__ __nv_bfloat16 g_W2b[HH*HH];
__device__ __nv_bfloat16 g_W3b[HH*HH];
__device__ __nv_bfloat16 g_outWb[(size_t)VOCAB*HH];
__device__ __nv_bfloat16 g_Wpackb[2048*HH];
__device__ float g_bpack[2048];
__device__ __nv_bfloat16 g_Wihx[3*HH*HH];
__device__ __nv_bfloat16 g_Wihc[3*HH*HH];
__device__ __nv_bfloat16 g_ebx[NSTEP*BB*HH];
__device__ float g_gix[(size_t)NSTEP*BB*3*HH];
__device__ __nv_bfloat16 g_encWc[(size_t)BL*3*HH];
__device__ float g_epart[4*BL];
__device__ __nv_bfloat16 g_hidb0[BB*HH];
__device__ __nv_bfloat16 g_hidb1[BB*HH];
__device__ float g_hid[BB*HH];
__device__ float g_hgh[BB*2048];                 // [hidatt(512) | gh(1536)]
__device__ float g_logits[BB*VOCAB];
__device__ int   g_tgt[BB*TT];
__device__ unsigned int g_cl2[64];
__device__ unsigned int g_cl3[64];
__device__ unsigned int g_ca;

__device__ __forceinline__ float tanha(float x) {
    float y; asm("tanh.approx.f32 %0, %1;" : "=f"(y) : "f"(x)); return y;
}

// ---------------- setup helpers ----------------
__global__ void convert_targets_k(const int* __restrict__ raw, int* __restrict__ tgt, int n)
{
    __shared__ int nonzero;
    if (threadIdx.x == 0) nonzero = 0;
    __syncthreads();
    int bad = 0;
    for (int i = 2*threadIdx.x + 1; i < n; i += 2*blockDim.x) bad |= raw[i];
    if (bad) atomicOr(&nonzero, 1);
    __syncthreads();
    int is64 = (nonzero == 0);
    for (int i = threadIdx.x; i < n; i += blockDim.x)
        tgt[i] = is64 ? raw[2*i] : raw[i];
}

__global__ void reset_cnt_k()
{
    if (threadIdx.x < 64) { g_cl2[threadIdx.x] = 0u; g_cl3[threadIdx.x] = 0u; }
    if (threadIdx.x == 0) g_ca = 0u;
}

__global__ void copyf_k(float* __restrict__ dst, const float* __restrict__ src, int n)
{
    int i = blockIdx.x*blockDim.x + threadIdx.x;
    if (i < n) dst[i] = src[i];
}

__global__ void cvtf2b_k(const float* __restrict__ src, __nv_bfloat16* __restrict__ dst, int n)
{
    int i = blockIdx.x*256 + threadIdx.x;
    if (i < n) dst[i] = __float2bfloat16(src[i]);
}

__global__ void pack_whhb_k(const float* __restrict__ W1, const float* __restrict__ Whh,
                            const float* __restrict__ bhh,
                            __nv_bfloat16* __restrict__ Wp, float* __restrict__ bp)
{
    int idx = blockIdx.x * 256 + threadIdx.x;
    int nn = idx >> 9, k = idx & 511;
    float v = (nn < 512) ? W1[nn*1024 + 512 + k] : Whh[(nn-512)*512 + k];
    Wp[idx] = __float2bfloat16(v);
    if (idx < 2048) bp[idx] = (idx < 512) ? 0.f : bhh[idx - 512];
}

__global__ void pack_wih_k(const float* __restrict__ Wih,
                           __nv_bfloat16* __restrict__ Wx, __nv_bfloat16* __restrict__ Wc)
{
    int idx = blockIdx.x * 256 + threadIdx.x;
    int n = idx >> 9, k = idx & 511;
    Wx[idx] = __float2bfloat16(Wih[n*1024 + k]);
    Wc[idx] = __float2bfloat16(Wih[n*1024 + 512 + k]);
}

__global__ void gather_embed_k(const float* __restrict__ embed_W, const int* __restrict__ tgt,
                               __nv_bfloat16* __restrict__ ebx)
{
    int r = blockIdx.x;
    int t = r >> 7, b = r & 127;
    int row = tgt[b*TT + t];
    const float4* src = (const float4*)(embed_W + (size_t)row*HH);
    __nv_bfloat16* dst = ebx + (size_t)r*HH;
    for (int c = threadIdx.x; c < HH/4; c += 128) {
        float4 v = src[c];
        __nv_bfloat162 p0; p0.x = __float2bfloat16(v.x); p0.y = __float2bfloat16(v.y);
        __nv_bfloat162 p1; p1.x = __float2bfloat16(v.z); p1.y = __float2bfloat16(v.w);
        *(__nv_bfloat162*)(dst + c*4)     = p0;
        *(__nv_bfloat162*)(dst + c*4 + 2) = p1;
    }
}

// ---------------- TF32 GEMM (one-time encpart only) ----------------
#define PITCH 20
__device__ __forceinline__ uint32_t f2tf(float x) {
    uint32_t u; asm("cvt.rna.tf32.f32 %0, %1;" : "=r"(u) : "f"(x)); return u;
}

__global__ __launch_bounds__(256)
void gemm_tf32_k(const float* __restrict__ A, const float* __restrict__ W,
                 const float* __restrict__ bias, float* __restrict__ C,
                 int M, int N, int K, int ldA, int ldW, int act)
{
    __shared__ float As[128*PITCH];
    __shared__ float Ws[128*PITCH];
    const int tid  = threadIdx.x;
    const int lane = tid & 31;
    const int wid  = tid >> 5;
    const int warpM = wid >> 2;
    const int warpN = wid & 3;
    const int gid = lane >> 2;
    const int tig = lane & 3;
    const int bm = blockIdx.y * 128;
    const int bn = blockIdx.x * 128;

    const int r0 = tid >> 2;
    const int q0 = (tid & 3) * 4;
    const float* Ag0 = A + (size_t)(bm + r0)      * ldA + q0;
    const float* Ag1 = A + (size_t)(bm + r0 + 64) * ldA + q0;
    const float* Wg0 = W + (size_t)(bn + r0)      * ldW + q0;
    const float* Wg1 = W + (size_t)(bn + r0 + 64) * ldW + q0;
    const int s0 = r0 * PITCH + q0;
    const int s1 = s0 + 64 * PITCH;

    float acc[4][4][4];
#pragma unroll
    for (int mt = 0; mt < 4; mt++)
#pragma unroll
        for (int nt = 0; nt < 4; nt++)
#pragma unroll
            for (int r = 0; r < 4; r++) acc[mt][nt][r] = 0.f;

    const int KT = K >> 4;
    float4 av0, av1, wv0, wv1;
    av0 = *(const float4*)(Ag0); av1 = *(const float4*)(Ag1);
    wv0 = *(const float4*)(Wg0); wv1 = *(const float4*)(Wg1);
    {
        uint4 t;
        t.x=f2tf(av0.x); t.y=f2tf(av0.y); t.z=f2tf(av0.z); t.w=f2tf(av0.w);
        *(uint4*)(As + s0) = t;
        t.x=f2tf(av1.x); t.y=f2tf(av1.y); t.z=f2tf(av1.z); t.w=f2tf(av1.w);
        *(uint4*)(As + s1) = t;
        t.x=f2tf(wv0.x); t.y=f2tf(wv0.y); t.z=f2tf(wv0.z); t.w=f2tf(wv0.w);
        *(uint4*)(Ws + s0) = t;
        t.x=f2tf(wv1.x); t.y=f2tf(wv1.y); t.z=f2tf(wv1.z); t.w=f2tf(wv1.w);
        *(uint4*)(Ws + s1) = t;
    }

    for (int kt = 0; kt < KT; kt++) {
        __syncthreads();
        if (kt + 1 < KT) {
            int k0 = (kt + 1) << 4;
            av0 = *(const float4*)(Ag0 + k0); av1 = *(const float4*)(Ag1 + k0);
            wv0 = *(const float4*)(Wg0 + k0); wv1 = *(const float4*)(Wg1 + k0);
        }
#pragma unroll
        for (int ks = 0; ks < 16; ks += 8) {
            uint32_t af[4][4], bf[4][2];
#pragma unroll
            for (int mt = 0; mt < 4; mt++) {
                const float* p = &As[(warpM*64 + mt*16 + gid) * PITCH + ks + tig];
                af[mt][0] = __float_as_uint(p[0]);
                af[mt][1] = __float_as_uint(p[8*PITCH]);
                af[mt][2] = __float_as_uint(p[4]);
                af[mt][3] = __float_as_uint(p[8*PITCH + 4]);
            }
#pragma unroll
            for (int nt = 0; nt < 4; nt++) {
                const float* p = &Ws[(warpN*32 + nt*8 + gid) * PITCH + ks + tig];
                bf[nt][0] = __float_as_uint(p[0]);
                bf[nt][1] = __float_as_uint(p[4]);
            }
#pragma unroll
            for (int mt = 0; mt < 4; mt++)
#pragma unroll
                for (int nt = 0; nt < 4; nt++) {
                    float* d = acc[mt][nt];
                    asm volatile(
                        "mma.sync.aligned.m16n8k8.row.col.f32.tf32.tf32.f32 "
                        "{%0,%1,%2,%3},{%4,%5,%6,%7},{%8,%9},{%0,%1,%2,%3};"
                        : "+f"(d[0]), "+f"(d[1]), "+f"(d[2]), "+f"(d[3])
                        : "r"(af[mt][0]), "r"(af[mt][1]), "r"(af[mt][2]), "r"(af[mt][3]),
                          "r"(bf[nt][0]), "r"(bf[nt][1]));
                }
        }
        __syncthreads();
        if (kt + 1 < KT) {
            uint4 t;
            t.x=f2tf(av0.x); t.y=f2tf(av0.y); t.z=f2tf(av0.z); t.w=f2tf(av0.w);
            *(uint4*)(As + s0) = t;
            t.x=f2tf(av1.x); t.y=f2tf(av1.y); t.z=f2tf(av1.z); t.w=f2tf(av1.w);
            *(uint4*)(As + s1) = t;
            t.x=f2tf(wv0.x); t.y=f2tf(wv0.y); t.z=f2tf(wv0.z); t.w=f2tf(wv0.w);
            *(uint4*)(Ws + s0) = t;
            t.x=f2tf(wv1.x); t.y=f2tf(wv1.y); t.z=f2tf(wv1.z); t.w=f2tf(wv1.w);
            *(uint4*)(Ws + s1) = t;
        }
    }

#pragma unroll
    for (int mt = 0; mt < 4; mt++) {
        int row = bm + warpM*64 + mt*16 + gid;
#pragma unroll
        for (int nt = 0; nt < 4; nt++) {
            int col = bn + warpN*32 + nt*8 + tig*2;
            float b0 = bias ? bias[col]     : 0.f;
            float b1 = bias ? bias[col + 1] : 0.f;
            float v0 = acc[mt][nt][0] + b0;
            float v1 = acc[mt][nt][1] + b1;
            float v2 = acc[mt][nt][2] + b0;
            float v3 = acc[mt][nt][3] + b1;
            if (act) { v0 = tanhf(v0); v1 = tanhf(v1); v2 = tanhf(v2); v3 = tanhf(v3); }
            *(float2*)&C[(size_t)row       * N + col] = make_float2(v0, v1);
            *(float2*)&C[(size_t)(row + 8) * N + col] = make_float2(v2, v3);
        }
    }
}

// ---------------- BF16 GEMM core (cp.async 2-stage + ldmatrix) ----------------
#define PB 40
#define STAGE_ELEMS (128*PB)

__device__ __forceinline__ void cp16(uint32_t dst, const void* src) {
    asm volatile("cp.async.cg.shared.global [%0], [%1], 16;" :: "r"(dst), "l"(src));
}
__device__ __forceinline__ void ldsm4(uint32_t* r, uint32_t addr) {
    asm volatile("ldmatrix.sync.aligned.m8n8.x4.shared.b16 {%0,%1,%2,%3}, [%4];"
        : "=r"(r[0]), "=r"(r[1]), "=r"(r[2]), "=r"(r[3]) : "r"(addr));
}

__device__ __forceinline__ void gemm_bf16_body(
    __nv_bfloat16* As, __nv_bfloat16* Ws,
    const __nv_bfloat16* __restrict__ A, const __nv_bfloat16* __restrict__ W,
    const float* __restrict__ bias, void* __restrict__ Cout,
    int N, int K, int ldA, int ldW, int act, int out_bf16, int bm, int bn)
{
    const int tid  = threadIdx.x;
    const int lane = tid & 31;
    const int wid  = tid >> 5;
    const int warpM = wid >> 2;
    const int warpN = wid & 3;
    const int gid = lane >> 2;
    const int tig = lane & 3;

    const int row_ld = tid >> 1;
    const int col_ld = (tid & 1) * 16;
    const __nv_bfloat16* Ag = A + (size_t)(bm + row_ld) * ldA + col_ld;
    const __nv_bfloat16* Wg = W + (size_t)(bn + row_ld) * ldW + col_ld;
    const uint32_t sA0 = (uint32_t)__cvta_generic_to_shared(As);
    const uint32_t sW0 = (uint32_t)__cvta_generic_to_shared(Ws);
    const uint32_t sAst = sA0 + (row_ld*PB + col_ld)*2;
    const uint32_t sWst = sW0 + (row_ld*PB + col_ld)*2;
    const uint32_t stageB = STAGE_ELEMS*2;

    const int a_row = lane & 15;
    const int a_k   = (lane >> 4) << 3;
    const int b_row = (lane & 7) | ((lane & 16) >> 1);
    const int b_k   = lane & 8;
    uint32_t aaddr[4], baddr[2];
#pragma unroll
    for (int mt = 0; mt < 4; mt++)
        aaddr[mt] = sA0 + ((warpM*64 + mt*16 + a_row)*PB + a_k)*2;
#pragma unroll
    for (int p = 0; p < 2; p++)
        baddr[p] = sW0 + ((warpN*32 + p*16 + b_row)*PB + b_k)*2;

    float acc[4][4][4];
#pragma unroll
    for (int mt = 0; mt < 4; mt++)
#pragma unroll
        for (int nt = 0; nt < 4; nt++)
#pragma unroll
            for (int r = 0; r < 4; r++) acc[mt][nt][r] = 0.f;

    const int KT = K >> 5;

    cp16(sAst,      Ag);
    cp16(sAst + 16, Ag + 8);
    cp16(sWst,      Wg);
    cp16(sWst + 16, Wg + 8);
    asm volatile("cp.async.commit_group;" ::: "memory");

    for (int kt = 0; kt < KT; kt++) {
        const uint32_t boff = (kt & 1) * stageB;
        if (kt + 1 < KT) {
            const uint32_t nb = ((kt + 1) & 1) * stageB;
            const __nv_bfloat16* ag = Ag + (kt + 1) * 32;
            const __nv_bfloat16* wg = Wg + (kt + 1) * 32;
            cp16(sAst + nb,      ag);
            cp16(sAst + nb + 16, ag + 8);
            cp16(sWst + nb,      wg);
            cp16(sWst + nb + 16, wg + 8);
            asm volatile("cp.async.commit_group;" ::: "memory");
            asm volatile("cp.async.wait_group 1;" ::: "memory");
        } else {
            asm volatile("cp.async.wait_group 0;" ::: "memory");
        }
        __syncthreads();

#pragma unroll
        for (int kk = 0; kk < 2; kk++) {
            uint32_t af[4][4], bfr[2][4];
#pragma unroll
            for (int mt = 0; mt < 4; mt++)
                ldsm4(af[mt], aaddr[mt] + boff + kk*32);
#pragma unroll
            for (int p = 0; p < 2; p++)
                ldsm4(bfr[p], baddr[p] + boff + kk*32);
#pragma unroll
            for (int mt = 0; mt < 4; mt++)
#pragma unroll
                for (int nt = 0; nt < 4; nt++) {
                    float* d = acc[mt][nt];
                    asm volatile(
                        "mma.sync.aligned.m16n8k16.row.col.f32.bf16.bf16.f32 "
                        "{%0,%1,%2,%3},{%4,%5,%6,%7},{%8,%9},{%0,%1,%2,%3};"
                        : "+f"(d[0]), "+f"(d[1]), "+f"(d[2]), "+f"(d[3])
                        : "r"(af[mt][0]), "r"(af[mt][1]), "r"(af[mt][2]), "r"(af[mt][3]),
                          "r"(bfr[nt>>1][(nt&1)*2]), "r"(bfr[nt>>1][(nt&1)*2+1]));
                }
        }
        __syncthreads();
    }

#pragma unroll
    for (int mt = 0; mt < 4; mt++) {
        int row = bm + warpM*64 + mt*16 + gid;
#pragma unroll
        for (int nt = 0; nt < 4; nt++) {
            int col = bn + warpN*32 + nt*8 + tig*2;
            float b0 = bias ? bias[col]     : 0.f;
            float b1 = bias ? bias[col + 1] : 0.f;
            float v0 = acc[mt][nt][0] + b0;
            float v1 = acc[mt][nt][1] + b1;
            float v2 = acc[mt][nt][2] + b0;
            float v3 = acc[mt][nt][3] + b1;
            if (act) { v0 = tanha(v0); v1 = tanha(v1); v2 = tanha(v2); v3 = tanha(v3); }
            if (out_bf16) {
                __nv_bfloat16* Cb = (__nv_bfloat16*)Cout;
                __nv_bfloat162 lo; lo.x = __float2bfloat16(v0); lo.y = __float2bfloat16(v1);
                __nv_bfloat162 hi; hi.x = __float2bfloat16(v2); hi.y = __float2bfloat16(v3);
                *(__nv_bfloat162*)&Cb[(size_t)row       * N + col] = lo;
                *(__nv_bfloat162*)&Cb[(size_t)(row + 8) * N + col] = hi;
            } else {
                float* Cf = (float*)Cout;
                *(float2*)&Cf[(size_t)row       * N + col] = make_float2(v0, v1);
                *(float2*)&Cf[(size_t)(row + 8) * N + col] = make_float2(v2, v3);
            }
        }
    }
}

__global__ __launch_bounds__(256)
void gemm_bf16_k(const __nv_bfloat16* __restrict__ A, const __nv_bfloat16* __restrict__ W,
                 const float* __restrict__ bias, void* __restrict__ Cout,
                 int N, int K, int ldA, int ldW, int act, int out_bf16)
{
    __shared__ __nv_bfloat16 As[2*STAGE_ELEMS];
    __shared__ __nv_bfloat16 Ws[2*STAGE_ELEMS];
    gemm_bf16_body(As, Ws, A, W, bias, Cout, N, K, ldA, ldW, act, out_bf16,
                   blockIdx.y*128, blockIdx.x*128);
}

// ---------------- megastep: L2 -> L3+e -> alpha/GRU -> hgh in ONE kernel ----------------
__global__ __launch_bounds__(256)
void megastep_k(const __nv_bfloat16* __restrict__ encpb, float* __restrict__ hgh,
                const __nv_bfloat16* __restrict__ W2b, const float* __restrict__ b2,
                __nv_bfloat16* __restrict__ a2b,
                const __nv_bfloat16* __restrict__ W3b, const float* __restrict__ b3,
                const float* __restrict__ v, float* __restrict__ epart,
                const __nv_bfloat16* __restrict__ encWc, const float* __restrict__ gix,
                float* __restrict__ hid, __nv_bfloat16* __restrict__ hidb_next,
                const __nv_bfloat16* __restrict__ Wpackb, const float* __restrict__ bpack,
                int t)
{
    __shared__ __nv_bfloat16 As[2*STAGE_ELEMS];
    __shared__ __nv_bfloat16 Ws[2*STAGE_ELEMS];
    __shared__ float vsh[128];
    __shared__ float esh4[4][128];
    __shared__ float e[LL];

    const int tid  = threadIdx.x;
    const int lane = tid & 31;
    const int wid  = tid >> 5;
    const int warpM = wid >> 2;
    const int warpN = wid & 3;
    const int gid = lane >> 2;
    const int tig = lane & 3;
    const int grp = blockIdx.x >> 2;
    const int bni = blockIdx.x & 3;
    const int bm = grp * 128;
    const int bn = bni * 128;

    const int row_ld = tid >> 1;
    const int col_ld = (tid & 1) * 16;
    const uint32_t sA0 = (uint32_t)__cvta_generic_to_shared(As);
    const uint32_t sW0 = (uint32_t)__cvta_generic_to_shared(Ws);
    const uint32_t sAst = sA0 + (row_ld*PB + col_ld)*2;
    const uint32_t sWst = sW0 + (row_ld*PB + col_ld)*2;
    const uint32_t stageB = STAGE_ELEMS*2;

    const int a_row = lane & 15;
    const int a_k   = (lane >> 4) << 3;
    const int b_row = (lane & 7) | ((lane & 16) >> 1);
    const int b_k   = lane & 8;
    uint32_t aaddr[4], baddr[2];
#pragma unroll
    for (int mt = 0; mt < 4; mt++)
        aaddr[mt] = sA0 + ((warpM*64 + mt*16 + a_row)*PB + a_k)*2;
#pragma unroll
    for (int p = 0; p < 2; p++)
        baddr[p] = sW0 + ((warpN*32 + p*16 + b_row)*PB + b_k)*2;

    // ================= PHASE 1: L2 GEMM (fused tanh(encpb + hidatt)) =================
    {
        const int brow = (bm + row_ld) >> 6;
        const __nv_bfloat16* Ag = encpb + (size_t)(bm + row_ld) * HH + col_ld;
        const float* Hg = hgh + brow*2048 + col_ld;
        const __nv_bfloat16* Wg = W2b + (size_t)(bn + row_ld) * HH + col_ld;

        float acc[4][4][4];
#pragma unroll
        for (int mt = 0; mt < 4; mt++)
#pragma unroll
            for (int nt = 0; nt < 4; nt++)
#pragma unroll
                for (int r = 0; r < 4; r++) acc[mt][nt][r] = 0.f;

        cp16(sWst,      Wg);
        cp16(sWst + 16, Wg + 8);
        asm volatile("cp.async.commit_group;" ::: "memory");

        for (int kt = 0; kt < 16; kt++) {
            const uint32_t boff = (kt & 1) * stageB;
            {
                const __nv_bfloat16* ag = Ag + kt*32;
                uint4 e0 = *(const uint4*)(ag);
                uint4 e1 = *(const uint4*)(ag + 8);
                const float* hp = Hg + kt*32;
                float4 h0 = *(const float4*)(hp);
                float4 h1 = *(const float4*)(hp + 4);
                float4 h2 = *(const float4*)(hp + 8);
                float4 h3 = *(const float4*)(hp + 12);
                float hf[16] = {h0.x,h0.y,h0.z,h0.w, h1.x,h1.y,h1.z,h1.w,
                                h2.x,h2.y,h2.z,h2.w, h3.x,h3.y,h3.z,h3.w};
                uint4 o0, o1;
                const __nv_bfloat162* pe = (const __nv_bfloat162*)&e0;
                __nv_bfloat162* po = (__nv_bfloat162*)&o0;
#pragma unroll
                for (int q = 0; q < 4; q++) {
                    float2 f = __bfloat1622float2(pe[q]);
                    __nv_bfloat162 r;
                    r.x = __float2bfloat16(tanha(f.x + hf[2*q]));
                    r.y = __float2bfloat16(tanha(f.y + hf[2*q+1]));
                    po[q] = r;
                }
                pe = (const __nv_bfloat162*)&e1;
                po = (__nv_bfloat162*)&o1;
#pragma unroll
                for (int q = 0; q < 4; q++) {
                    float2 f = __bfloat1622float2(pe[q]);
                    __nv_bfloat162 r;
                    r.x = __float2bfloat16(tanha(f.x + hf[8 + 2*q]));
                    r.y = __float2bfloat16(tanha(f.y + hf[8 + 2*q+1]));
                    po[q] = r;
                }
                __nv_bfloat16* sA = As + (kt & 1)*STAGE_ELEMS + row_ld*PB + col_ld;
                *(uint4*)(sA)     = o0;
                *(uint4*)(sA + 8) = o1;
            }
            if (kt + 1 < 16) {
                const uint32_t nb = ((kt + 1) & 1) * stageB;
                const __nv_bfloat16* wg = Wg + (kt + 1) * 32;
                cp16(sWst + nb,      wg);
                cp16(sWst + nb + 16, wg + 8);
                asm volatile("cp.async.commit_group;" ::: "memory");
                asm volatile("cp.async.wait_group 1;" ::: "memory");
            } else {
                asm volatile("cp.async.wait_group 0;" ::: "memory");
            }
            __syncthreads();
#pragma unroll
            for (int kk = 0; kk < 2; kk++) {
                uint32_t af[4][4], bfr[2][4];
#pragma unroll
                for (int mt = 0; mt < 4; mt++)
                    ldsm4(af[mt], aaddr[mt] + boff + kk*32);
#pragma unroll
                for (int p = 0; p < 2; p++)
                    ldsm4(bfr[p], baddr[p] + boff + kk*32);
#pragma unroll
                for (int mt = 0; mt < 4; mt++)
#pragma unroll
                    for (int nt = 0; nt < 4; nt++) {
                        float* d = acc[mt][nt];
                        asm volatile(
                            "mma.sync.aligned.m16n8k16.row.col.f32.bf16.bf16.f32 "
                            "{%0,%1,%2,%3},{%4,%5,%6,%7},{%8,%9},{%0,%1,%2,%3};"
                            : "+f"(d[0]), "+f"(d[1]), "+f"(d[2]), "+f"(d[3])
                            : "r"(af[mt][0]), "r"(af[mt][1]), "r"(af[mt][2]), "r"(af[mt][3]),
                              "r"(bfr[nt>>1][(nt&1)*2]), "r"(bfr[nt>>1][(nt&1)*2+1]));
                    }
            }
            __syncthreads();
        }

#pragma unroll
        for (int mt = 0; mt < 4; mt++) {
            int row = bm + warpM*64 + mt*16 + gid;
#pragma unroll
            for (int nt = 0; nt < 4; nt++) {
                int col = bn + warpN*32 + nt*8 + tig*2;
                float b0 = b2[col], b1 = b2[col + 1];
                __nv_bfloat162 lo, hi;
                lo.x = __float2bfloat16(tanha(acc[mt][nt][0] + b0));
                lo.y = __float2bfloat16(tanha(acc[mt][nt][1] + b1));
                hi.x = __float2bfloat16(tanha(acc[mt][nt][2] + b0));
                hi.y = __float2bfloat16(tanha(acc[mt][nt][3] + b1));
                *(__nv_bfloat162*)&a2b[(size_t)row       * HH + col] = lo;
                *(__nv_bfloat162*)&a2b[(size_t)(row + 8) * HH + col] = hi;
            }
        }
        __threadfence();
        __syncthreads();
        if (tid == 0) atomicAdd(&g_cl2[grp], 1u);
    }

    // ================= PHASE 2: L3 GEMM + e-dot partials =================
    {
        if (tid == 0) {
            const unsigned tgt4 = 4u*(unsigned)(t + 1);
            while (atomicAdd(&g_cl2[grp], 0u) < tgt4) __nanosleep(32);
        }
        __syncthreads();
        __threadfence();

        if (tid < 128) vsh[tid] = v[bn + tid];
        const __nv_bfloat16* Ag = a2b + (size_t)(bm + row_ld) * HH + col_ld;
        const __nv_bfloat16* Wg = W3b + (size_t)(bn + row_ld) * HH + col_ld;

        float acc[4][4][4];
#pragma unroll
        for (int mt = 0; mt < 4; mt++)
#pragma unroll
            for (int nt = 0; nt < 4; nt++)
#pragma unroll
                for (int r = 0; r < 4; r++) acc[mt][nt][r] = 0.f;

        cp16(sAst,      Ag);
        cp16(sAst + 16, Ag + 8);
        cp16(sWst,      Wg);
        cp16(sWst + 16, Wg + 8);
        asm volatile("cp.async.commit_group;" ::: "memory");

        for (int kt = 0; kt < 16; kt++) {
            const uint32_t boff = (kt & 1) * stageB;
            if (kt + 1 < 16) {
                const uint32_t nb = ((kt + 1) & 1) * stageB;
                const __nv_bfloat16* ag = Ag + (kt + 1) * 32;
                const __nv_bfloat16* wg = Wg + (kt + 1) * 32;
                cp16(sAst + nb,      ag);
                cp16(sAst + nb + 16, ag + 8);
                cp16(sWst + nb,      wg);
                cp16(sWst + nb + 16, wg + 8);
                asm volatile("cp.async.commit_group;" ::: "memory");
                asm volatile("cp.async.wait_group 1;" ::: "memory");
            } else {
                asm volatile("cp.async.wait_group 0;" ::: "memory");
            }
            __syncthreads();
#pragma unroll
            for (int kk = 0; kk < 2; kk++) {
                uint32_t af[4][4], bfr[2][4];
#pragma unroll
                for (int mt = 0; mt < 4; mt++)
                    ldsm4(af[mt], aaddr[mt] + boff + kk*32);
#pragma unroll
                for (int p = 0; p < 2; p++)
                    ldsm4(bfr[p], baddr[p] + boff + kk*32);
#pragma unroll
                for (int mt = 0; mt < 4; mt++)
#pragma unroll
                    for (int nt = 0; nt < 4; nt++) {
                        float* d = acc[mt][nt];
                        asm volatile(
                            "mma.sync.aligned.m16n8k16.row.col.f32.bf16.bf16.f32 "
                            "{%0,%1,%2,%3},{%4,%5,%6,%7},{%8,%9},{%0,%1,%2,%3};"
                            : "+f"(d[0]), "+f"(d[1]), "+f"(d[2]), "+f"(d[3])
                            : "r"(af[mt][0]), "r"(af[mt][1]), "r"(af[mt][2]), "r"(af[mt][3]),
                              "r"(bfr[nt>>1][(nt&1)*2]), "r"(bfr[nt>>1][(nt&1)*2+1]));
                    }
            }
            __syncthreads();
        }

        float rsum[4][2];
#pragma unroll
        for (int mt = 0; mt < 4; mt++) { rsum[mt][0] = 0.f; rsum[mt][1] = 0.f; }
#pragma unroll
        for (int mt = 0; mt < 4; mt++) {
#pragma unroll
            for (int nt = 0; nt < 4; nt++) {
                int cl = warpN*32 + nt*8 + tig*2;
                float b0 = b3[bn + cl], b1 = b3[bn + cl + 1];
                float vv0 = vsh[cl], vv1 = vsh[cl + 1];
                rsum[mt][0] += tanha(acc[mt][nt][0] + b0)*vv0 + tanha(acc[mt][nt][1] + b1)*vv1;
                rsum[mt][1] += tanha(acc[mt][nt][2] + b0)*vv0 + tanha(acc[mt][nt][3] + b1)*vv1;
            }
        }
#pragma unroll
        for (int mt = 0; mt < 4; mt++) {
#pragma unroll
            for (int r = 0; r < 2; r++) {
                float val = rsum[mt][r];
                val += __shfl_xor_sync(0xffffffffu, val, 1);
                val += __shfl_xor_sync(0xffffffffu, val, 2);
                if (tig == 0)
                    esh4[warpN][warpM*64 + mt*16 + gid + r*8] = val;
            }
        }
        __syncthreads();
        if (tid < 128)
            epart[bni*BL + bm + tid] =
                (esh4[0][tid] + esh4[1][tid]) + (esh4[2][tid] + esh4[3][tid]);
        __threadfence();
        __syncthreads();
        if (tid == 0) atomicAdd(&g_cl3[grp], 1u);
    }

    // ================= PHASE 3: alpha/softmax -> gic -> GRU (bni < 2) =================
    if (bni < 2) {
        const int b = grp*2 + bni;
        if (tid == 0) {
            const unsigned tgt4 = 4u*(unsigned)(t + 1);
            while (atomicAdd(&g_cl3[grp], 0u) < tgt4) __nanosleep(32);
        }
        __syncthreads();
        __threadfence();

        if (tid < LL) {
            int r = b*LL + tid;
            e[tid] = (epart[r] + epart[BL + r]) + (epart[2*BL + r] + epart[3*BL + r]);
        }
        __syncthreads();
        if (tid == 0) {
            float mx = -1e30f;
            for (int l = 0; l < LL; l++) mx = fmaxf(mx, e[l]);
            float sum = 0.f;
            for (int l = 0; l < LL; l++) { e[l] = expf(e[l] - mx); sum += e[l]; }
            float inv = 1.f / sum;
            for (int l = 0; l < LL; l++) e[l] *= inv;
        }
        __syncthreads();

        float2 ar = make_float2(0.f,0.f), az = make_float2(0.f,0.f), an = make_float2(0.f,0.f);
        const int j0 = tid * 2;
        const __nv_bfloat16* base = encWc + (size_t)b*LL*1536;
#pragma unroll 4
        for (int l = 0; l < LL; l++) {
            float al = e[l];
            const __nv_bfloat16* row = base + (size_t)l*1536;
            float2 r0 = __bfloat1622float2(*(const __nv_bfloat162*)(row + j0));
            float2 r1 = __bfloat1622float2(*(const __nv_bfloat162*)(row + 512 + j0));
            float2 r2 = __bfloat1622float2(*(const __nv_bfloat162*)(row + 1024 + j0));
            ar.x += al*r0.x; ar.y += al*r0.y;
            az.x += al*r1.x; az.y += al*r1.y;
            an.x += al*r2.x; an.y += al*r2.y;
        }

        const float* gx = gix + ((size_t)t*BB + b)*1536;
        const float* gh = hgh + b*2048 + 512;
        float gr[2] = {ar.x, ar.y}, gz[2] = {az.x, az.y}, gn[2] = {an.x, an.y};
#pragma unroll
        for (int q = 0; q < 2; q++) {
            int j = j0 + q;
            float rr = gx[j]        + gr[q] + gh[j];
            float zz = gx[512 + j]  + gz[q] + gh[512 + j];
            float nn = gx[1024 + j] + gn[q];
            float r = 1.f / (1.f + expf(-rr));
            float z = 1.f / (1.f + expf(-zz));
            float n = tanhf(nn + r * gh[1024 + j]);
            float h = (1.f - z) * n + z * hid[b*HH + j];
            hid[b*HH + j]       = h;
            hidb_next[b*HH + j] = __float2bfloat16(h);
        }
        __threadfence();
        __syncthreads();
        if (tid == 0) atomicAdd(&g_ca, 1u);
    }

    // ================= PHASE 4: hgh(t+1) GEMM (blocks 0..15) =================
    if (blockIdx.x < 16) {
        if (tid == 0) {
            const unsigned tgtA = 128u*(unsigned)(t + 1);
            while (atomicAdd(&g_ca, 0u) < tgtA) __nanosleep(64);
        }
        __syncthreads();
        __threadfence();
        gemm_bf16_body(As, Ws, hidb_next, Wpackb, bpack, hgh, 2048, HH, HH, HH, 0, 0,
                       0, (int)blockIdx.x * 128);
    }
}

// ---------------- standalone log-softmax ----------------
__global__ __launch_bounds__(256)
void lsm_k(const float* __restrict__ logits, float* __restrict__ out, int t_lsm)
{
    const int tid = threadIdx.x;
    int b = blockIdx.x;
    const float4* row = (const float4*)(logits + (size_t)b * VOCAB);
    __shared__ float rm[256], rs[256];
    float m = -1e30f, s = 0.f;
    for (int i = tid; i < VOCAB/4; i += 256) {
        float4 vv = row[i];
#define ONLN(x) { float d = (x) - m; if (d > 0.f) { s = s*expf(-d) + 1.f; m = (x); } else s += expf(d); }
        ONLN(vv.x) ONLN(vv.y) ONLN(vv.z) ONLN(vv.w)
#undef ONLN
    }
    rm[tid] = m; rs[tid] = s; __syncthreads();
    for (int st = 128; st > 0; st >>= 1) {
        if (tid < st) {
            float m2 = rm[tid+st], s2 = rs[tid+st];
            float M = fmaxf(rm[tid], m2);
            rs[tid] = rs[tid]*expf(rm[tid]-M) + s2*expf(m2-M);
            rm[tid] = M;
        }
        __syncthreads();
    }
    float lse = rm[0] + logf(rs[0]);
    float4* orow = (float4*)(out + ((size_t)b * NSTEP + t_lsm) * VOCAB);
    for (int i = tid; i < VOCAB/4; i += 256) {
        float4 vv = row[i];
        vv.x -= lse; vv.y -= lse; vv.z -= lse; vv.w -= lse;
        orow[i] = vv;
    }
}

// ---------------- launch ----------------
extern "C" void kernel_launch(void* const* d_in, const int* in_sizes, int n_in,
                              void* d_out, int out_size)
{
    const float* enc     = (const float*)d_in[0];
    const float* enc_hid = (const float*)d_in[1];
    const int*   traw    = (const int*)  d_in[2];
    const float* embed_W = (const float*)d_in[3];
    const float* att_W1  = (const float*)d_in[4];
    const float* att_b1  = (const float*)d_in[5];
    const float* att_W2  = (const float*)d_in[6];
    const float* att_b2  = (const float*)d_in[7];
    const float* att_W3  = (const float*)d_in[8];
    const float* att_b3  = (const float*)d_in[9];
    const float* att_v   = (const float*)d_in[10];
    const float* gru_Wih = (const float*)d_in[11];
    const float* gru_Whh = (const float*)d_in[12];
    const float* gru_bih = (const float*)d_in[13];
    const float* gru_bhh = (const float*)d_in[14];
    const float* out_W   = (const float*)d_in[15];
    const float* out_b   = (const float*)d_in[16];
    float* out = (float*)d_out;

    float *encpart, *hid, *hgh, *gix, *logits, *bpack, *epart;
    __nv_bfloat16 *encpb, *encb, *a2b, *W2b, *W3b, *outWb, *hidb0, *hidb1;
    __nv_bfloat16 *Wpackb, *Wihx, *Wihc, *ebx, *encWc;
    int *tgt;
    cudaGetSymbolAddress((void**)&encpart, g_encpart);
    cudaGetSymbolAddress((void**)&encpb,   g_encpb);
    cudaGetSymbolAddress((void**)&encb,    g_encb);
    cudaGetSymbolAddress((void**)&a2b,     g_a2b);
    cudaGetSymbolAddress((void**)&W2b,     g_W2b);
    cudaGetSymbolAddress((void**)&W3b,     g_W3b);
    cudaGetSymbolAddress((void**)&outWb,   g_outWb);
    cudaGetSymbolAddress((void**)&Wpackb,  g_Wpackb);
    cudaGetSymbolAddress((void**)&bpack,   g_bpack);
    cudaGetSymbolAddress((void**)&Wihx,    g_Wihx);
    cudaGetSymbolAddress((void**)&Wihc,    g_Wihc);
    cudaGetSymbolAddress((void**)&ebx,     g_ebx);
    cudaGetSymbolAddress((void**)&gix,     g_gix);
    cudaGetSymbolAddress((void**)&encWc,   g_encWc);
    cudaGetSymbolAddress((void**)&epart,   g_epart);
    cudaGetSymbolAddress((void**)&hidb0,   g_hidb0);
    cudaGetSymbolAddress((void**)&hidb1,   g_hidb1);
    cudaGetSymbolAddress((void**)&hid,     g_hid);
    cudaGetSymbolAddress((void**)&hgh,     g_hgh);
    cudaGetSymbolAddress((void**)&logits,  g_logits);
    cudaGetSymbolAddress((void**)&tgt,     g_tgt);
    __nv_bfloat16* hb[2] = {hidb0, hidb1};

    static cudaStream_t s2 = nullptr;
    static cudaEvent_t evF = nullptr, evJ = nullptr, evV = nullptr;
    if (!s2) {
        cudaStreamCreateWithFlags(&s2, cudaStreamNonBlocking);
        cudaEventCreateWithFlags(&evF, cudaEventDisableTiming);
        cudaEventCreateWithFlags(&evJ, cudaEventDisableTiming);
        cudaEventCreateWithFlags(&evV, cudaEventDisableTiming);
    }

    // ---- setup (fork: encpart tf32 chain + vocab weight cvt on s2) ----
    cudaEventRecord(evF, 0);
    cudaStreamWaitEvent(s2, evF, 0);
    gemm_tf32_k<<<dim3(HH/128, BL/128), 256, 0, s2>>>(enc, att_W1, att_b1, encpart,
                                                      BL, HH, HH, HH, 2*HH, 0);
    cvtf2b_k<<<(BL*HH)/256, 256, 0, s2>>>(encpart, encpb, BL*HH);
    cvtf2b_k<<<(VOCAB*HH)/256, 256, 0, s2>>>(out_W, outWb, VOCAB*HH);

    reset_cnt_k<<<1, 64>>>();
    convert_targets_k<<<1, 256>>>(traw, tgt, BB*TT);
    copyf_k<<<(BB*HH + 255)/256, 256>>>(hid, enc_hid, BB*HH);
    cvtf2b_k<<<(BB*HH)/256, 256>>>(enc_hid, hidb0, BB*HH);
    pack_whhb_k<<<(2048*HH)/256, 256>>>(att_W1, gru_Whh, gru_bhh, Wpackb, bpack);
    pack_wih_k<<<(3*HH*HH)/256, 256>>>(gru_Wih, Wihx, Wihc);
    cvtf2b_k<<<(HH*HH)/256, 256>>>(att_W2, W2b, HH*HH);
    cvtf2b_k<<<(HH*HH)/256, 256>>>(att_W3, W3b, HH*HH);
    cvtf2b_k<<<(BL*HH)/256, 256>>>(enc, encb, BL*HH);
    gather_embed_k<<<NSTEP*BB, 128>>>(embed_W, tgt, ebx);
    gemm_bf16_k<<<dim3(1536/128, NSTEP*BB/128), 256>>>(ebx, Wihx, gru_bih, gix,
                                                       1536, HH, HH, HH, 0, 0);
    gemm_bf16_k<<<dim3(1536/128, BL/128), 256>>>(encb, Wihc, nullptr, encWc,
                                                 1536, HH, HH, HH, 0, 1);
    gemm_bf16_k<<<dim3(2048/128, 1), 256>>>(hidb0, Wpackb, bpack, hgh,
                                            2048, HH, HH, HH, 0, 0);
    cudaEventRecord(evJ, s2);
    cudaStreamWaitEvent(0, evJ, 0);

    // ---- recurrent loop: 1 megastep launch + hidden vocab branch ----
    for (int t = 0; t < NSTEP; t++) {
        if (t > 0) {
            cudaEventRecord(evF, 0);
            cudaStreamWaitEvent(s2, evF, 0);
            gemm_bf16_k<<<dim3(NVB, 1), 256, 0, s2>>>(hb[t & 1], outWb, out_b, logits,
                                                      VOCAB, HH, HH, HH, 0, 0);
            cudaEventRecord(evV, s2);
            lsm_k<<<BB, 256, 0, s2>>>(logits, out, t - 1);
            cudaStreamWaitEvent(0, evV, 0);
        }
        megastep_k<<<256, 256>>>(encpb, hgh, W2b, att_b2, a2b, W3b, att_b3, att_v,
                                 epart, encWc, gix, hid, hb[(t + 1) & 1],
                                 Wpackb, bpack, t);
    }
    // join + tail: vocab(30) + logsoftmax(30)
    cudaEventRecord(evJ, s2);
    cudaStreamWaitEvent(0, evJ, 0);
    gemm_bf16_k<<<dim3(NVB, 1), 256>>>(hb[NSTEP & 1], outWb, out_b, logits,
                                       VOCAB, HH, HH, HH, 0, 0);
    lsm_k<<<BB, 256>>>(logits, out, NSTEP - 1);

    (void)in_sizes; (void)n_in; (void)out_size;
}

// round 13
// speedup vs baseline: 1.1418x; 1.1418x over previous
#include <cuda_runtime.h>
#include <cuda_bf16.h>
#include <math.h>
#include <stdint.h>

#define BB 128
#define LL 64
#define HH 512
#define VOCAB 32000
#define TT 32
#define NSTEP 31
#define BL (BB*LL)       // 8192
#define NVB (VOCAB/128)  // 250

// ---------------- scratch (device globals; no allocation) ----------------
__device__ float g_encpart[BL*HH];
__device__ __nv_bfloat16 g_encpb[BL*HH];
__device__ __nv_bfloat16 g_encb[BL*HH];
__device__ __nv_bfloat16 g_a2b[BL*HH];
__device__ __nv_bfloat16 g_W2b[HH*HH];
__device__ __nv_bfloat16 g_W3b[HH*HH];
__device__ __nv_bfloat16 g_outWb[(size_t)VOCAB*HH];
__device__ __nv_bfloat16 g_Wpackb[2048*HH];
__device__ float g_bpack[2048];
__device__ __nv_bfloat16 g_Wihx[3*HH*HH];
__device__ __nv_bfloat16 g_Wihc[3*HH*HH];
__device__ __nv_bfloat16 g_ebx[NSTEP*BB*HH];
__device__ float g_gix[(size_t)NSTEP*BB*3*HH];
__device__ __nv_bfloat16 g_encWc[(size_t)BL*3*HH];
__device__ float g_epart[4*BL];
__device__ __nv_bfloat16 g_hidb0[BB*HH];
__device__ __nv_bfloat16 g_hidb1[BB*HH];
__device__ float g_hid[BB*HH];
__device__ float g_hgh[BB*2048];                 // [hidatt(512) | gh(1536)]
__device__ float g_logits[BB*VOCAB];
__device__ int   g_tgt[BB*TT];
__device__ unsigned int g_cl3[64];
__device__ unsigned int g_ca;

__device__ __forceinline__ float tanha(float x) {
    float y; asm("tanh.approx.f32 %0, %1;" : "=f"(y) : "f"(x)); return y;
}

// ---------------- setup helpers ----------------
__global__ void convert_targets_k(const int* __restrict__ raw, int* __restrict__ tgt, int n)
{
    __shared__ int nonzero;
    if (threadIdx.x == 0) nonzero = 0;
    __syncthreads();
    int bad = 0;
    for (int i = 2*threadIdx.x + 1; i < n; i += 2*blockDim.x) bad |= raw[i];
    if (bad) atomicOr(&nonzero, 1);
    __syncthreads();
    int is64 = (nonzero == 0);
    for (int i = threadIdx.x; i < n; i += blockDim.x)
        tgt[i] = is64 ? raw[2*i] : raw[i];
}

__global__ void reset_cnt_k()
{
    if (threadIdx.x < 64) g_cl3[threadIdx.x] = 0u;
    if (threadIdx.x == 0) g_ca = 0u;
}

__global__ void copyf_k(float* __restrict__ dst, const float* __restrict__ src, int n)
{
    int i = blockIdx.x*blockDim.x + threadIdx.x;
    if (i < n) dst[i] = src[i];
}

__global__ void cvtf2b_k(const float* __restrict__ src, __nv_bfloat16* __restrict__ dst, int n)
{
    int i = blockIdx.x*256 + threadIdx.x;
    if (i < n) dst[i] = __float2bfloat16(src[i]);
}

__global__ void pack_whhb_k(const float* __restrict__ W1, const float* __restrict__ Whh,
                            const float* __restrict__ bhh,
                            __nv_bfloat16* __restrict__ Wp, float* __restrict__ bp)
{
    int idx = blockIdx.x * 256 + threadIdx.x;
    int nn = idx >> 9, k = idx & 511;
    float v = (nn < 512) ? W1[nn*1024 + 512 + k] : Whh[(nn-512)*512 + k];
    Wp[idx] = __float2bfloat16(v);
    if (idx < 2048) bp[idx] = (idx < 512) ? 0.f : bhh[idx - 512];
}

__global__ void pack_wih_k(const float* __restrict__ Wih,
                           __nv_bfloat16* __restrict__ Wx, __nv_bfloat16* __restrict__ Wc)
{
    int idx = blockIdx.x * 256 + threadIdx.x;
    int n = idx >> 9, k = idx & 511;
    Wx[idx] = __float2bfloat16(Wih[n*1024 + k]);
    Wc[idx] = __float2bfloat16(Wih[n*1024 + 512 + k]);
}

__global__ void gather_embed_k(const float* __restrict__ embed_W, const int* __restrict__ tgt,
                               __nv_bfloat16* __restrict__ ebx)
{
    int r = blockIdx.x;
    int t = r >> 7, b = r & 127;
    int row = tgt[b*TT + t];
    const float4* src = (const float4*)(embed_W + (size_t)row*HH);
    __nv_bfloat16* dst = ebx + (size_t)r*HH;
    for (int c = threadIdx.x; c < HH/4; c += 128) {
        float4 v = src[c];
        __nv_bfloat162 p0; p0.x = __float2bfloat16(v.x); p0.y = __float2bfloat16(v.y);
        __nv_bfloat162 p1; p1.x = __float2bfloat16(v.z); p1.y = __float2bfloat16(v.w);
        *(__nv_bfloat162*)(dst + c*4)     = p0;
        *(__nv_bfloat162*)(dst + c*4 + 2) = p1;
    }
}

// ---------------- TF32 GEMM (one-time encpart only) ----------------
#define PITCH 20
__device__ __forceinline__ uint32_t f2tf(float x) {
    uint32_t u; asm("cvt.rna.tf32.f32 %0, %1;" : "=r"(u) : "f"(x)); return u;
}

__global__ __launch_bounds__(256)
void gemm_tf32_k(const float* __restrict__ A, const float* __restrict__ W,
                 const float* __restrict__ bias, float* __restrict__ C,
                 int M, int N, int K, int ldA, int ldW, int act)
{
    __shared__ float As[128*PITCH];
    __shared__ float Ws[128*PITCH];
    const int tid  = threadIdx.x;
    const int lane = tid & 31;
    const int wid  = tid >> 5;
    const int warpM = wid >> 2;
    const int warpN = wid & 3;
    const int gid = lane >> 2;
    const int tig = lane & 3;
    const int bm = blockIdx.y * 128;
    const int bn = blockIdx.x * 128;

    const int r0 = tid >> 2;
    const int q0 = (tid & 3) * 4;
    const float* Ag0 = A + (size_t)(bm + r0)      * ldA + q0;
    const float* Ag1 = A + (size_t)(bm + r0 + 64) * ldA + q0;
    const float* Wg0 = W + (size_t)(bn + r0)      * ldW + q0;
    const float* Wg1 = W + (size_t)(bn + r0 + 64) * ldW + q0;
    const int s0 = r0 * PITCH + q0;
    const int s1 = s0 + 64 * PITCH;

    float acc[4][4][4];
#pragma unroll
    for (int mt = 0; mt < 4; mt++)
#pragma unroll
        for (int nt = 0; nt < 4; nt++)
#pragma unroll
            for (int r = 0; r < 4; r++) acc[mt][nt][r] = 0.f;

    const int KT = K >> 4;
    float4 av0, av1, wv0, wv1;
    av0 = *(const float4*)(Ag0); av1 = *(const float4*)(Ag1);
    wv0 = *(const float4*)(Wg0); wv1 = *(const float4*)(Wg1);
    {
        uint4 t;
        t.x=f2tf(av0.x); t.y=f2tf(av0.y); t.z=f2tf(av0.z); t.w=f2tf(av0.w);
        *(uint4*)(As + s0) = t;
        t.x=f2tf(av1.x); t.y=f2tf(av1.y); t.z=f2tf(av1.z); t.w=f2tf(av1.w);
        *(uint4*)(As + s1) = t;
        t.x=f2tf(wv0.x); t.y=f2tf(wv0.y); t.z=f2tf(wv0.z); t.w=f2tf(wv0.w);
        *(uint4*)(Ws + s0) = t;
        t.x=f2tf(wv1.x); t.y=f2tf(wv1.y); t.z=f2tf(wv1.z); t.w=f2tf(wv1.w);
        *(uint4*)(Ws + s1) = t;
    }

    for (int kt = 0; kt < KT; kt++) {
        __syncthreads();
        if (kt + 1 < KT) {
            int k0 = (kt + 1) << 4;
            av0 = *(const float4*)(Ag0 + k0); av1 = *(const float4*)(Ag1 + k0);
            wv0 = *(const float4*)(Wg0 + k0); wv1 = *(const float4*)(Wg1 + k0);
        }
#pragma unroll
        for (int ks = 0; ks < 16; ks += 8) {
            uint32_t af[4][4], bf[4][2];
#pragma unroll
            for (int mt = 0; mt < 4; mt++) {
                const float* p = &As[(warpM*64 + mt*16 + gid) * PITCH + ks + tig];
                af[mt][0] = __float_as_uint(p[0]);
                af[mt][1] = __float_as_uint(p[8*PITCH]);
                af[mt][2] = __float_as_uint(p[4]);
                af[mt][3] = __float_as_uint(p[8*PITCH + 4]);
            }
#pragma unroll
            for (int nt = 0; nt < 4; nt++) {
                const float* p = &Ws[(warpN*32 + nt*8 + gid) * PITCH + ks + tig];
                bf[nt][0] = __float_as_uint(p[0]);
                bf[nt][1] = __float_as_uint(p[4]);
            }
#pragma unroll
            for (int mt = 0; mt < 4; mt++)
#pragma unroll
                for (int nt = 0; nt < 4; nt++) {
                    float* d = acc[mt][nt];
                    asm volatile(
                        "mma.sync.aligned.m16n8k8.row.col.f32.tf32.tf32.f32 "
                        "{%0,%1,%2,%3},{%4,%5,%6,%7},{%8,%9},{%0,%1,%2,%3};"
                        : "+f"(d[0]), "+f"(d[1]), "+f"(d[2]), "+f"(d[3])
                        : "r"(af[mt][0]), "r"(af[mt][1]), "r"(af[mt][2]), "r"(af[mt][3]),
                          "r"(bf[nt][0]), "r"(bf[nt][1]));
                }
        }
        __syncthreads();
        if (kt + 1 < KT) {
            uint4 t;
            t.x=f2tf(av0.x); t.y=f2tf(av0.y); t.z=f2tf(av0.z); t.w=f2tf(av0.w);
            *(uint4*)(As + s0) = t;
            t.x=f2tf(av1.x); t.y=f2tf(av1.y); t.z=f2tf(av1.z); t.w=f2tf(av1.w);
            *(uint4*)(As + s1) = t;
            t.x=f2tf(wv0.x); t.y=f2tf(wv0.y); t.z=f2tf(wv0.z); t.w=f2tf(wv0.w);
            *(uint4*)(Ws + s0) = t;
            t.x=f2tf(wv1.x); t.y=f2tf(wv1.y); t.z=f2tf(wv1.z); t.w=f2tf(wv1.w);
            *(uint4*)(Ws + s1) = t;
        }
    }

#pragma unroll
    for (int mt = 0; mt < 4; mt++) {
        int row = bm + warpM*64 + mt*16 + gid;
#pragma unroll
        for (int nt = 0; nt < 4; nt++) {
            int col = bn + warpN*32 + nt*8 + tig*2;
            float b0 = bias ? bias[col]     : 0.f;
            float b1 = bias ? bias[col + 1] : 0.f;
            float v0 = acc[mt][nt][0] + b0;
            float v1 = acc[mt][nt][1] + b1;
            float v2 = acc[mt][nt][2] + b0;
            float v3 = acc[mt][nt][3] + b1;
            if (act) { v0 = tanhf(v0); v1 = tanhf(v1); v2 = tanhf(v2); v3 = tanhf(v3); }
            *(float2*)&C[(size_t)row       * N + col] = make_float2(v0, v1);
            *(float2*)&C[(size_t)(row + 8) * N + col] = make_float2(v2, v3);
        }
    }
}

// ---------------- BF16 GEMM core (cp.async 2-stage + ldmatrix) ----------------
#define PB 40
#define STAGE_ELEMS (128*PB)

__device__ __forceinline__ void cp16(uint32_t dst, const void* src) {
    asm volatile("cp.async.cg.shared.global [%0], [%1], 16;" :: "r"(dst), "l"(src));
}
__device__ __forceinline__ void ldsm4(uint32_t* r, uint32_t addr) {
    asm volatile("ldmatrix.sync.aligned.m8n8.x4.shared.b16 {%0,%1,%2,%3}, [%4];"
        : "=r"(r[0]), "=r"(r[1]), "=r"(r[2]), "=r"(r[3]) : "r"(addr));
}

__device__ __forceinline__ void gemm_bf16_body(
    __nv_bfloat16* As, __nv_bfloat16* Ws,
    const __nv_bfloat16* __restrict__ A, const __nv_bfloat16* __restrict__ W,
    const float* __restrict__ bias, void* __restrict__ Cout,
    int N, int K, int ldA, int ldW, int act, int out_bf16, int bm, int bn)
{
    const int tid  = threadIdx.x;
    const int lane = tid & 31;
    const int wid  = tid >> 5;
    const int warpM = wid >> 2;
    const int warpN = wid & 3;
    const int gid = lane >> 2;
    const int tig = lane & 3;

    const int row_ld = tid >> 1;
    const int col_ld = (tid & 1) * 16;
    const __nv_bfloat16* Ag = A + (size_t)(bm + row_ld) * ldA + col_ld;
    const __nv_bfloat16* Wg = W + (size_t)(bn + row_ld) * ldW + col_ld;
    const uint32_t sA0 = (uint32_t)__cvta_generic_to_shared(As);
    const uint32_t sW0 = (uint32_t)__cvta_generic_to_shared(Ws);
    const uint32_t sAst = sA0 + (row_ld*PB + col_ld)*2;
    const uint32_t sWst = sW0 + (row_ld*PB + col_ld)*2;
    const uint32_t stageB = STAGE_ELEMS*2;

    const int a_row = lane & 15;
    const int a_k   = (lane >> 4) << 3;
    const int b_row = (lane & 7) | ((lane & 16) >> 1);
    const int b_k   = lane & 8;
    uint32_t aaddr[4], baddr[2];
#pragma unroll
    for (int mt = 0; mt < 4; mt++)
        aaddr[mt] = sA0 + ((warpM*64 + mt*16 + a_row)*PB + a_k)*2;
#pragma unroll
    for (int p = 0; p < 2; p++)
        baddr[p] = sW0 + ((warpN*32 + p*16 + b_row)*PB + b_k)*2;

    float acc[4][4][4];
#pragma unroll
    for (int mt = 0; mt < 4; mt++)
#pragma unroll
        for (int nt = 0; nt < 4; nt++)
#pragma unroll
            for (int r = 0; r < 4; r++) acc[mt][nt][r] = 0.f;

    const int KT = K >> 5;

    cp16(sAst,      Ag);
    cp16(sAst + 16, Ag + 8);
    cp16(sWst,      Wg);
    cp16(sWst + 16, Wg + 8);
    asm volatile("cp.async.commit_group;" ::: "memory");

    for (int kt = 0; kt < KT; kt++) {
        const uint32_t boff = (kt & 1) * stageB;
        if (kt + 1 < KT) {
            const uint32_t nb = ((kt + 1) & 1) * stageB;
            const __nv_bfloat16* ag = Ag + (kt + 1) * 32;
            const __nv_bfloat16* wg = Wg + (kt + 1) * 32;
            cp16(sAst + nb,      ag);
            cp16(sAst + nb + 16, ag + 8);
            cp16(sWst + nb,      wg);
            cp16(sWst + nb + 16, wg + 8);
            asm volatile("cp.async.commit_group;" ::: "memory");
            asm volatile("cp.async.wait_group 1;" ::: "memory");
        } else {
            asm volatile("cp.async.wait_group 0;" ::: "memory");
        }
        __syncthreads();

#pragma unroll
        for (int kk = 0; kk < 2; kk++) {
            uint32_t af[4][4], bfr[2][4];
#pragma unroll
            for (int mt = 0; mt < 4; mt++)
                ldsm4(af[mt], aaddr[mt] + boff + kk*32);
#pragma unroll
            for (int p = 0; p < 2; p++)
                ldsm4(bfr[p], baddr[p] + boff + kk*32);
#pragma unroll
            for (int mt = 0; mt < 4; mt++)
#pragma unroll
                for (int nt = 0; nt < 4; nt++) {
                    float* d = acc[mt][nt];
                    asm volatile(
                        "mma.sync.aligned.m16n8k16.row.col.f32.bf16.bf16.f32 "
                        "{%0,%1,%2,%3},{%4,%5,%6,%7},{%8,%9},{%0,%1,%2,%3};"
                        : "+f"(d[0]), "+f"(d[1]), "+f"(d[2]), "+f"(d[3])
                        : "r"(af[mt][0]), "r"(af[mt][1]), "r"(af[mt][2]), "r"(af[mt][3]),
                          "r"(bfr[nt>>1][(nt&1)*2]), "r"(bfr[nt>>1][(nt&1)*2+1]));
                }
        }
        __syncthreads();
    }

#pragma unroll
    for (int mt = 0; mt < 4; mt++) {
        int row = bm + warpM*64 + mt*16 + gid;
#pragma unroll
        for (int nt = 0; nt < 4; nt++) {
            int col = bn + warpN*32 + nt*8 + tig*2;
            float b0 = bias ? bias[col]     : 0.f;
            float b1 = bias ? bias[col + 1] : 0.f;
            float v0 = acc[mt][nt][0] + b0;
            float v1 = acc[mt][nt][1] + b1;
            float v2 = acc[mt][nt][2] + b0;
            float v3 = acc[mt][nt][3] + b1;
            if (act) { v0 = tanha(v0); v1 = tanha(v1); v2 = tanha(v2); v3 = tanha(v3); }
            if (out_bf16) {
                __nv_bfloat16* Cb = (__nv_bfloat16*)Cout;
                __nv_bfloat162 lo; lo.x = __float2bfloat16(v0); lo.y = __float2bfloat16(v1);
                __nv_bfloat162 hi; hi.x = __float2bfloat16(v2); hi.y = __float2bfloat16(v3);
                *(__nv_bfloat162*)&Cb[(size_t)row       * N + col] = lo;
                *(__nv_bfloat162*)&Cb[(size_t)(row + 8) * N + col] = hi;
            } else {
                float* Cf = (float*)Cout;
                *(float2*)&Cf[(size_t)row       * N + col] = make_float2(v0, v1);
                *(float2*)&Cf[(size_t)(row + 8) * N + col] = make_float2(v2, v3);
            }
        }
    }
}

__global__ __launch_bounds__(256)
void gemm_bf16_k(const __nv_bfloat16* __restrict__ A, const __nv_bfloat16* __restrict__ W,
                 const float* __restrict__ bias, void* __restrict__ Cout,
                 int N, int K, int ldA, int ldW, int act, int out_bf16)
{
    __shared__ __nv_bfloat16 As[2*STAGE_ELEMS];
    __shared__ __nv_bfloat16 Ws[2*STAGE_ELEMS];
    gemm_bf16_body(As, Ws, A, W, bias, Cout, N, K, ldA, ldW, act, out_bf16,
                   blockIdx.y*128, blockIdx.x*128);
}

// ---------------- L2 GEMM with fused tanh(encpb + hidatt) A-operand ----------------
__global__ __launch_bounds__(256)
void megaL2_k(const __nv_bfloat16* __restrict__ encpb, const float* __restrict__ hgh,
              const __nv_bfloat16* __restrict__ W2b, const float* __restrict__ b2,
              __nv_bfloat16* __restrict__ a2b)
{
    __shared__ __nv_bfloat16 As[2*STAGE_ELEMS];
    __shared__ __nv_bfloat16 Ws[2*STAGE_ELEMS];
    const int bm = (blockIdx.x >> 2) * 128;
    const int bn = (blockIdx.x & 3) * 128;
    const int tid  = threadIdx.x;
    const int lane = tid & 31;
    const int wid  = tid >> 5;
    const int warpM = wid >> 2;
    const int warpN = wid & 3;
    const int gid = lane >> 2;
    const int tig = lane & 3;

    const int row_ld = tid >> 1;
    const int col_ld = (tid & 1) * 16;
    const int brow = (bm + row_ld) >> 6;
    const __nv_bfloat16* Ag = encpb + (size_t)(bm + row_ld) * HH + col_ld;
    const float* Hg = hgh + brow*2048 + col_ld;
    const __nv_bfloat16* Wg = W2b + (size_t)(bn + row_ld) * HH + col_ld;
    const uint32_t sA0 = (uint32_t)__cvta_generic_to_shared(As);
    const uint32_t sW0 = (uint32_t)__cvta_generic_to_shared(Ws);
    const uint32_t sWst = sW0 + (row_ld*PB + col_ld)*2;
    const uint32_t stageB = STAGE_ELEMS*2;

    const int a_row = lane & 15;
    const int a_k   = (lane >> 4) << 3;
    const int b_row = (lane & 7) | ((lane & 16) >> 1);
    const int b_k   = lane & 8;
    uint32_t aaddr[4], baddr[2];
#pragma unroll
    for (int mt = 0; mt < 4; mt++)
        aaddr[mt] = sA0 + ((warpM*64 + mt*16 + a_row)*PB + a_k)*2;
#pragma unroll
    for (int p = 0; p < 2; p++)
        baddr[p] = sW0 + ((warpN*32 + p*16 + b_row)*PB + b_k)*2;

    float acc[4][4][4];
#pragma unroll
    for (int mt = 0; mt < 4; mt++)
#pragma unroll
        for (int nt = 0; nt < 4; nt++)
#pragma unroll
            for (int r = 0; r < 4; r++) acc[mt][nt][r] = 0.f;

    cp16(sWst,      Wg);
    cp16(sWst + 16, Wg + 8);
    asm volatile("cp.async.commit_group;" ::: "memory");

    for (int kt = 0; kt < 16; kt++) {
        const uint32_t boff = (kt & 1) * stageB;
        {
            const __nv_bfloat16* ag = Ag + kt*32;
            uint4 e0 = *(const uint4*)(ag);
            uint4 e1 = *(const uint4*)(ag + 8);
            const float* hp = Hg + kt*32;
            float4 h0 = *(const float4*)(hp);
            float4 h1 = *(const float4*)(hp + 4);
            float4 h2 = *(const float4*)(hp + 8);
            float4 h3 = *(const float4*)(hp + 12);
            float hf[16] = {h0.x,h0.y,h0.z,h0.w, h1.x,h1.y,h1.z,h1.w,
                            h2.x,h2.y,h2.z,h2.w, h3.x,h3.y,h3.z,h3.w};
            uint4 o0, o1;
            const __nv_bfloat162* pe = (const __nv_bfloat162*)&e0;
            __nv_bfloat162* po = (__nv_bfloat162*)&o0;
#pragma unroll
            for (int q = 0; q < 4; q++) {
                float2 f = __bfloat1622float2(pe[q]);
                __nv_bfloat162 r;
                r.x = __float2bfloat16(tanha(f.x + hf[2*q]));
                r.y = __float2bfloat16(tanha(f.y + hf[2*q+1]));
                po[q] = r;
            }
            pe = (const __nv_bfloat162*)&e1;
            po = (__nv_bfloat162*)&o1;
#pragma unroll
            for (int q = 0; q < 4; q++) {
                float2 f = __bfloat1622float2(pe[q]);
                __nv_bfloat162 r;
                r.x = __float2bfloat16(tanha(f.x + hf[8 + 2*q]));
                r.y = __float2bfloat16(tanha(f.y + hf[8 + 2*q+1]));
                po[q] = r;
            }
            __nv_bfloat16* sA = As + (kt & 1)*STAGE_ELEMS + row_ld*PB + col_ld;
            *(uint4*)(sA)     = o0;
            *(uint4*)(sA + 8) = o1;
        }
        if (kt + 1 < 16) {
            const uint32_t nb = ((kt + 1) & 1) * stageB;
            const __nv_bfloat16* wg = Wg + (kt + 1) * 32;
            cp16(sWst + nb,      wg);
            cp16(sWst + nb + 16, wg + 8);
            asm volatile("cp.async.commit_group;" ::: "memory");
            asm volatile("cp.async.wait_group 1;" ::: "memory");
        } else {
            asm volatile("cp.async.wait_group 0;" ::: "memory");
        }
        __syncthreads();
#pragma unroll
        for (int kk = 0; kk < 2; kk++) {
            uint32_t af[4][4], bfr[2][4];
#pragma unroll
            for (int mt = 0; mt < 4; mt++)
                ldsm4(af[mt], aaddr[mt] + boff + kk*32);
#pragma unroll
            for (int p = 0; p < 2; p++)
                ldsm4(bfr[p], baddr[p] + boff + kk*32);
#pragma unroll
            for (int mt = 0; mt < 4; mt++)
#pragma unroll
                for (int nt = 0; nt < 4; nt++) {
                    float* d = acc[mt][nt];
                    asm volatile(
                        "mma.sync.aligned.m16n8k16.row.col.f32.bf16.bf16.f32 "
                        "{%0,%1,%2,%3},{%4,%5,%6,%7},{%8,%9},{%0,%1,%2,%3};"
                        : "+f"(d[0]), "+f"(d[1]), "+f"(d[2]), "+f"(d[3])
                        : "r"(af[mt][0]), "r"(af[mt][1]), "r"(af[mt][2]), "r"(af[mt][3]),
                          "r"(bfr[nt>>1][(nt&1)*2]), "r"(bfr[nt>>1][(nt&1)*2+1]));
                }
        }
        __syncthreads();
    }

#pragma unroll
    for (int mt = 0; mt < 4; mt++) {
        int row = bm + warpM*64 + mt*16 + gid;
#pragma unroll
        for (int nt = 0; nt < 4; nt++) {
            int col = bn + warpN*32 + nt*8 + tig*2;
            float b0 = b2[col], b1 = b2[col + 1];
            __nv_bfloat162 lo, hi;
            lo.x = __float2bfloat16(tanha(acc[mt][nt][0] + b0));
            lo.y = __float2bfloat16(tanha(acc[mt][nt][1] + b1));
            hi.x = __float2bfloat16(tanha(acc[mt][nt][2] + b0));
            hi.y = __float2bfloat16(tanha(acc[mt][nt][3] + b1));
            *(__nv_bfloat162*)&a2b[(size_t)row       * HH + col] = lo;
            *(__nv_bfloat162*)&a2b[(size_t)(row + 8) * HH + col] = hi;
        }
    }
}

// ---------------- L3alpha: L3 GEMM + e-partials, then alpha/GRU (bni<2), then hgh (blk<16) ----------------
__global__ __launch_bounds__(256)
void L3alpha_k(const __nv_bfloat16* __restrict__ a2b, const __nv_bfloat16* __restrict__ W3b,
               const float* __restrict__ b3, const float* __restrict__ v,
               float* __restrict__ epart,
               const __nv_bfloat16* __restrict__ encWc, const float* __restrict__ gix,
               float* __restrict__ hgh, float* __restrict__ hid,
               __nv_bfloat16* __restrict__ hidb_next,
               const __nv_bfloat16* __restrict__ Wpackb, const float* __restrict__ bpack,
               int t)
{
    __shared__ __nv_bfloat16 As[2*STAGE_ELEMS];
    __shared__ __nv_bfloat16 Ws[2*STAGE_ELEMS];
    __shared__ float vsh[128];
    __shared__ float esh4[4][128];
    __shared__ float e[LL];
    const int tid = threadIdx.x;
    const int grp = blockIdx.x >> 2;
    const int bni = blockIdx.x & 3;
    const int bm = grp * 128;
    const int bn = bni * 128;
    const int lane = tid & 31;
    const int wid  = tid >> 5;
    const int warpM = wid >> 2;
    const int warpN = wid & 3;
    const int gid = lane >> 2;
    const int tig = lane & 3;

    // ---------- phase 1: L3 GEMM tile + e-partials ----------
    {
        if (tid < 128) vsh[tid] = v[bn + tid];
        const int row_ld = tid >> 1;
        const int col_ld = (tid & 1) * 16;
        const __nv_bfloat16* Ag = a2b + (size_t)(bm + row_ld) * HH + col_ld;
        const __nv_bfloat16* Wg = W3b + (size_t)(bn + row_ld) * HH + col_ld;
        const uint32_t sA0 = (uint32_t)__cvta_generic_to_shared(As);
        const uint32_t sW0 = (uint32_t)__cvta_generic_to_shared(Ws);
        const uint32_t sAst = sA0 + (row_ld*PB + col_ld)*2;
        const uint32_t sWst = sW0 + (row_ld*PB + col_ld)*2;
        const uint32_t stageB = STAGE_ELEMS*2;

        const int a_row = lane & 15;
        const int a_k   = (lane >> 4) << 3;
        const int b_row = (lane & 7) | ((lane & 16) >> 1);
        const int b_k   = lane & 8;
        uint32_t aaddr[4], baddr[2];
#pragma unroll
        for (int mt = 0; mt < 4; mt++)
            aaddr[mt] = sA0 + ((warpM*64 + mt*16 + a_row)*PB + a_k)*2;
#pragma unroll
        for (int p = 0; p < 2; p++)
            baddr[p] = sW0 + ((warpN*32 + p*16 + b_row)*PB + b_k)*2;

        float acc[4][4][4];
#pragma unroll
        for (int mt = 0; mt < 4; mt++)
#pragma unroll
            for (int nt = 0; nt < 4; nt++)
#pragma unroll
                for (int r = 0; r < 4; r++) acc[mt][nt][r] = 0.f;

        cp16(sAst,      Ag);
        cp16(sAst + 16, Ag + 8);
        cp16(sWst,      Wg);
        cp16(sWst + 16, Wg + 8);
        asm volatile("cp.async.commit_group;" ::: "memory");

        for (int kt = 0; kt < 16; kt++) {
            const uint32_t boff = (kt & 1) * stageB;
            if (kt + 1 < 16) {
                const uint32_t nb = ((kt + 1) & 1) * stageB;
                const __nv_bfloat16* ag = Ag + (kt + 1) * 32;
                const __nv_bfloat16* wg = Wg + (kt + 1) * 32;
                cp16(sAst + nb,      ag);
                cp16(sAst + nb + 16, ag + 8);
                cp16(sWst + nb,      wg);
                cp16(sWst + nb + 16, wg + 8);
                asm volatile("cp.async.commit_group;" ::: "memory");
                asm volatile("cp.async.wait_group 1;" ::: "memory");
            } else {
                asm volatile("cp.async.wait_group 0;" ::: "memory");
            }
            __syncthreads();
#pragma unroll
            for (int kk = 0; kk < 2; kk++) {
                uint32_t af[4][4], bfr[2][4];
#pragma unroll
                for (int mt = 0; mt < 4; mt++)
                    ldsm4(af[mt], aaddr[mt] + boff + kk*32);
#pragma unroll
                for (int p = 0; p < 2; p++)
                    ldsm4(bfr[p], baddr[p] + boff + kk*32);
#pragma unroll
                for (int mt = 0; mt < 4; mt++)
#pragma unroll
                    for (int nt = 0; nt < 4; nt++) {
                        float* d = acc[mt][nt];
                        asm volatile(
                            "mma.sync.aligned.m16n8k16.row.col.f32.bf16.bf16.f32 "
                            "{%0,%1,%2,%3},{%4,%5,%6,%7},{%8,%9},{%0,%1,%2,%3};"
                            : "+f"(d[0]), "+f"(d[1]), "+f"(d[2]), "+f"(d[3])
                            : "r"(af[mt][0]), "r"(af[mt][1]), "r"(af[mt][2]), "r"(af[mt][3]),
                              "r"(bfr[nt>>1][(nt&1)*2]), "r"(bfr[nt>>1][(nt&1)*2+1]));
                    }
            }
            __syncthreads();
        }

        float rsum[4][2];
#pragma unroll
        for (int mt = 0; mt < 4; mt++) { rsum[mt][0] = 0.f; rsum[mt][1] = 0.f; }
#pragma unroll
        for (int mt = 0; mt < 4; mt++) {
#pragma unroll
            for (int nt = 0; nt < 4; nt++) {
                int cl = warpN*32 + nt*8 + tig*2;
                float b0 = b3[bn + cl], b1 = b3[bn + cl + 1];
                float vv0 = vsh[cl], vv1 = vsh[cl + 1];
                rsum[mt][0] += tanha(acc[mt][nt][0] + b0)*vv0 + tanha(acc[mt][nt][1] + b1)*vv1;
                rsum[mt][1] += tanha(acc[mt][nt][2] + b0)*vv0 + tanha(acc[mt][nt][3] + b1)*vv1;
            }
        }
#pragma unroll
        for (int mt = 0; mt < 4; mt++) {
#pragma unroll
            for (int r = 0; r < 2; r++) {
                float val = rsum[mt][r];
                val += __shfl_xor_sync(0xffffffffu, val, 1);
                val += __shfl_xor_sync(0xffffffffu, val, 2);
                if (tig == 0)
                    esh4[warpN][warpM*64 + mt*16 + gid + r*8] = val;
            }
        }
        __syncthreads();
        if (tid < 128)
            epart[bni*BL + bm + tid] =
                (esh4[0][tid] + esh4[1][tid]) + (esh4[2][tid] + esh4[3][tid]);
        __threadfence();
        __syncthreads();
        if (tid == 0) atomicAdd(&g_cl3[grp], 1u);
    }

    // ---------- phase 2: alpha/softmax -> gic -> GRU (bni < 2) ----------
    if (bni < 2) {
        const int b = grp*2 + bni;
        if (tid == 0) {
            const unsigned tgt4 = 4u*(unsigned)(t + 1);
            while (atomicAdd(&g_cl3[grp], 0u) < tgt4) __nanosleep(32);
        }
        __syncthreads();
        __threadfence();

        if (tid < LL) {
            int r = b*LL + tid;
            e[tid] = (epart[r] + epart[BL + r]) + (epart[2*BL + r] + epart[3*BL + r]);
        }
        __syncthreads();
        if (tid == 0) {
            float mx = -1e30f;
            for (int l = 0; l < LL; l++) mx = fmaxf(mx, e[l]);
            float sum = 0.f;
            for (int l = 0; l < LL; l++) { e[l] = expf(e[l] - mx); sum += e[l]; }
            float inv = 1.f / sum;
            for (int l = 0; l < LL; l++) e[l] *= inv;
        }
        __syncthreads();

        float2 ar = make_float2(0.f,0.f), az = make_float2(0.f,0.f), an = make_float2(0.f,0.f);
        const int j0 = tid * 2;
        const __nv_bfloat16* base = encWc + (size_t)b*LL*1536;
#pragma unroll 4
        for (int l = 0; l < LL; l++) {
            float al = e[l];
            const __nv_bfloat16* row = base + (size_t)l*1536;
            float2 r0 = __bfloat1622float2(*(const __nv_bfloat162*)(row + j0));
            float2 r1 = __bfloat1622float2(*(const __nv_bfloat162*)(row + 512 + j0));
            float2 r2 = __bfloat1622float2(*(const __nv_bfloat162*)(row + 1024 + j0));
            ar.x += al*r0.x; ar.y += al*r0.y;
            az.x += al*r1.x; az.y += al*r1.y;
            an.x += al*r2.x; an.y += al*r2.y;
        }

        const float* gx = gix + ((size_t)t*BB + b)*1536;
        const float* gh = hgh + b*2048 + 512;
        float gr[2] = {ar.x, ar.y}, gz[2] = {az.x, az.y}, gn[2] = {an.x, an.y};
#pragma unroll
        for (int q = 0; q < 2; q++) {
            int j = j0 + q;
            float rr = gx[j]        + gr[q] + gh[j];
            float zz = gx[512 + j]  + gz[q] + gh[512 + j];
            float nn = gx[1024 + j] + gn[q];
            float r = 1.f / (1.f + expf(-rr));
            float z = 1.f / (1.f + expf(-zz));
            float n = tanhf(nn + r * gh[1024 + j]);
            float h = (1.f - z) * n + z * hid[b*HH + j];
            hid[b*HH + j]       = h;
            hidb_next[b*HH + j] = __float2bfloat16(h);
        }
        __threadfence();
        __syncthreads();
        if (tid == 0) atomicAdd(&g_ca, 1u);
    }

    // ---------- phase 3: hgh(t+1) GEMM (blocks 0..15) ----------
    if (blockIdx.x < 16) {
        if (tid == 0) {
            const unsigned tgtA = 128u*(unsigned)(t + 1);
            while (atomicAdd(&g_ca, 0u) < tgtA) __nanosleep(64);
        }
        __syncthreads();
        __threadfence();
        gemm_bf16_body(As, Ws, hidb_next, Wpackb, bpack, hgh, 2048, HH, HH, HH, 0, 0,
                       0, (int)blockIdx.x * 128);
    }
}

// ---------------- standalone log-softmax ----------------
__global__ __launch_bounds__(256)
void lsm_k(const float* __restrict__ logits, float* __restrict__ out, int t_lsm)
{
    const int tid = threadIdx.x;
    int b = blockIdx.x;
    const float4* row = (const float4*)(logits + (size_t)b * VOCAB);
    __shared__ float rm[256], rs[256];
    float m = -1e30f, s = 0.f;
    for (int i = tid; i < VOCAB/4; i += 256) {
        float4 vv = row[i];
#define ONLN(x) { float d = (x) - m; if (d > 0.f) { s = s*expf(-d) + 1.f; m = (x); } else s += expf(d); }
        ONLN(vv.x) ONLN(vv.y) ONLN(vv.z) ONLN(vv.w)
#undef ONLN
    }
    rm[tid] = m; rs[tid] = s; __syncthreads();
    for (int st = 128; st > 0; st >>= 1) {
        if (tid < st) {
            float m2 = rm[tid+st], s2 = rs[tid+st];
            float M = fmaxf(rm[tid], m2);
            rs[tid] = rs[tid]*expf(rm[tid]-M) + s2*expf(m2-M);
            rm[tid] = M;
        }
        __syncthreads();
    }
    float lse = rm[0] + logf(rs[0]);
    float4* orow = (float4*)(out + ((size_t)b * NSTEP + t_lsm) * VOCAB);
    for (int i = tid; i < VOCAB/4; i += 256) {
        float4 vv = row[i];
        vv.x -= lse; vv.y -= lse; vv.z -= lse; vv.w -= lse;
        orow[i] = vv;
    }
}

// ---------------- launch ----------------
extern "C" void kernel_launch(void* const* d_in, const int* in_sizes, int n_in,
                              void* d_out, int out_size)
{
    const float* enc     = (const float*)d_in[0];
    const float* enc_hid = (const float*)d_in[1];
    const int*   traw    = (const int*)  d_in[2];
    const float* embed_W = (const float*)d_in[3];
    const float* att_W1  = (const float*)d_in[4];
    const float* att_b1  = (const float*)d_in[5];
    const float* att_W2  = (const float*)d_in[6];
    const float* att_b2  = (const float*)d_in[7];
    const float* att_W3  = (const float*)d_in[8];
    const float* att_b3  = (const float*)d_in[9];
    const float* att_v   = (const float*)d_in[10];
    const float* gru_Wih = (const float*)d_in[11];
    const float* gru_Whh = (const float*)d_in[12];
    const float* gru_bih = (const float*)d_in[13];
    const float* gru_bhh = (const float*)d_in[14];
    const float* out_W   = (const float*)d_in[15];
    const float* out_b   = (const float*)d_in[16];
    float* out = (float*)d_out;

    float *encpart, *hid, *hgh, *gix, *logits, *bpack, *epart;
    __nv_bfloat16 *encpb, *encb, *a2b, *W2b, *W3b, *outWb, *hidb0, *hidb1;
    __nv_bfloat16 *Wpackb, *Wihx, *Wihc, *ebx, *encWc;
    int *tgt;
    cudaGetSymbolAddress((void**)&encpart, g_encpart);
    cudaGetSymbolAddress((void**)&encpb,   g_encpb);
    cudaGetSymbolAddress((void**)&encb,    g_encb);
    cudaGetSymbolAddress((void**)&a2b,     g_a2b);
    cudaGetSymbolAddress((void**)&W2b,     g_W2b);
    cudaGetSymbolAddress((void**)&W3b,     g_W3b);
    cudaGetSymbolAddress((void**)&outWb,   g_outWb);
    cudaGetSymbolAddress((void**)&Wpackb,  g_Wpackb);
    cudaGetSymbolAddress((void**)&bpack,   g_bpack);
    cudaGetSymbolAddress((void**)&Wihx,    g_Wihx);
    cudaGetSymbolAddress((void**)&Wihc,    g_Wihc);
    cudaGetSymbolAddress((void**)&ebx,     g_ebx);
    cudaGetSymbolAddress((void**)&gix,     g_gix);
    cudaGetSymbolAddress((void**)&encWc,   g_encWc);
    cudaGetSymbolAddress((void**)&epart,   g_epart);
    cudaGetSymbolAddress((void**)&hidb0,   g_hidb0);
    cudaGetSymbolAddress((void**)&hidb1,   g_hidb1);
    cudaGetSymbolAddress((void**)&hid,     g_hid);
    cudaGetSymbolAddress((void**)&hgh,     g_hgh);
    cudaGetSymbolAddress((void**)&logits,  g_logits);
    cudaGetSymbolAddress((void**)&tgt,     g_tgt);
    __nv_bfloat16* hb[2] = {hidb0, hidb1};

    static cudaStream_t s2 = nullptr;
    static cudaEvent_t evF = nullptr, evJ = nullptr, evV = nullptr;
    if (!s2) {
        cudaStreamCreateWithFlags(&s2, cudaStreamNonBlocking);
        cudaEventCreateWithFlags(&evF, cudaEventDisableTiming);
        cudaEventCreateWithFlags(&evJ, cudaEventDisableTiming);
        cudaEventCreateWithFlags(&evV, cudaEventDisableTiming);
    }

    // ---- setup (fork: encpart tf32 chain + vocab weight cvt on s2) ----
    cudaEventRecord(evF, 0);
    cudaStreamWaitEvent(s2, evF, 0);
    gemm_tf32_k<<<dim3(HH/128, BL/128), 256, 0, s2>>>(enc, att_W1, att_b1, encpart,
                                                      BL, HH, HH, HH, 2*HH, 0);
    cvtf2b_k<<<(BL*HH)/256, 256, 0, s2>>>(encpart, encpb, BL*HH);
    cvtf2b_k<<<(VOCAB*HH)/256, 256, 0, s2>>>(out_W, outWb, VOCAB*HH);

    reset_cnt_k<<<1, 64>>>();
    convert_targets_k<<<1, 256>>>(traw, tgt, BB*TT);
    copyf_k<<<(BB*HH + 255)/256, 256>>>(hid, enc_hid, BB*HH);
    cvtf2b_k<<<(BB*HH)/256, 256>>>(enc_hid, hidb0, BB*HH);
    pack_whhb_k<<<(2048*HH)/256, 256>>>(att_W1, gru_Whh, gru_bhh, Wpackb, bpack);
    pack_wih_k<<<(3*HH*HH)/256, 256>>>(gru_Wih, Wihx, Wihc);
    cvtf2b_k<<<(HH*HH)/256, 256>>>(att_W2, W2b, HH*HH);
    cvtf2b_k<<<(HH*HH)/256, 256>>>(att_W3, W3b, HH*HH);
    cvtf2b_k<<<(BL*HH)/256, 256>>>(enc, encb, BL*HH);
    gather_embed_k<<<NSTEP*BB, 128>>>(embed_W, tgt, ebx);
    gemm_bf16_k<<<dim3(1536/128, NSTEP*BB/128), 256>>>(ebx, Wihx, gru_bih, gix,
                                                       1536, HH, HH, HH, 0, 0);
    gemm_bf16_k<<<dim3(1536/128, BL/128), 256>>>(encb, Wihc, nullptr, encWc,
                                                 1536, HH, HH, HH, 0, 1);
    gemm_bf16_k<<<dim3(2048/128, 1), 256>>>(hidb0, Wpackb, bpack, hgh,
                                            2048, HH, HH, HH, 0, 0);
    cudaEventRecord(evJ, s2);
    cudaStreamWaitEvent(0, evJ, 0);

    // ---- recurrent loop: megaL2 + L3alpha on stream 0; vocab+lsm hidden on s2 ----
    for (int t = 0; t < NSTEP; t++) {
        if (t > 0) {
            cudaEventRecord(evF, 0);
            cudaStreamWaitEvent(s2, evF, 0);
            gemm_bf16_k<<<dim3(NVB, 1), 256, 0, s2>>>(hb[t & 1], outWb, out_b, logits,
                                                      VOCAB, HH, HH, HH, 0, 0);
            cudaEventRecord(evV, s2);
            lsm_k<<<BB, 256, 0, s2>>>(logits, out, t - 1);
        }
        megaL2_k<<<256, 256>>>(encpb, hgh, W2b, att_b2, a2b);
        if (t > 0) cudaStreamWaitEvent(0, evV, 0);
        L3alpha_k<<<256, 256>>>(a2b, W3b, att_b3, att_v, epart, encWc, gix,
                                hgh, hid, hb[(t + 1) & 1], Wpackb, bpack, t);
    }
    // join + tail: vocab(30) + logsoftmax(30)
    cudaEventRecord(evJ, s2);
    cudaStreamWaitEvent(0, evJ, 0);
    gemm_bf16_k<<<dim3(NVB, 1), 256>>>(hb[NSTEP & 1], outWb, out_b, logits,
                                       VOCAB, HH, HH, HH, 0, 0);
    lsm_k<<<BB, 256>>>(logits, out, NSTEP - 1);

    (void)in_sizes; (void)n_in; (void)out_size;
}